// round 1
// baseline (speedup 1.0000x reference)
#include <cuda_runtime.h>
#include <math.h>

// Problem constants
#define T_STEPS 20
#define B_DIM   16384
#define P_DIM   256
#define H_DIM   512
#define S_DIM   512
#define C_DIM   128
#define SC_DIM  640     // S + C
#define TAUF    0.25f
#define OMTF    0.75f

// Scratch (static device globals — no runtime allocation allowed)
__device__ float g_hbuf[T_STEPS * B_DIM * H_DIM];  // Z, then a_hps carries (671 MB)
__device__ float g_ubuf[T_STEPS * B_DIM * S_DIM];  // U[t] = a_hps@W_hs + bias_s (671 MB)
__device__ float g_act0[B_DIM * SC_DIM];           // [a_s | a_css] double buffer
__device__ float g_act1[B_DIM * SC_DIM];
__device__ float g_in  [B_DIM * SC_DIM];           // [in_s | in_css] state
__device__ float g_wbig[SC_DIM * SC_DIM];          // [[W_ss, W_sc],[W_cs, 0]]

__device__ __forceinline__ float sigf(float x) { return 1.0f / (1.0f + expf(-x)); }

// ---------------------------------------------------------------------------
// Generic fp32 SGEMM: C[M,N] = A[M,K] @ B[K,N] (+epilogue per MODE)
// Tile: BM=128, BN=128, BK=16, 256 threads, 8x8 per-thread microtile.
// All problem dims are multiples of 128/16 -> no bounds checks.
// MODE 0: plain store
// MODE 1: +bias[n]
// MODE 2: fused recurrent step epilogue (leaky update + sigmoid + state write)
// ---------------------------------------------------------------------------
template<int MODE>
__global__ void __launch_bounds__(256, 2)
gemm_kernel(const float* __restrict__ A, const float* __restrict__ Bm,
            float* __restrict__ C, int M, int N, int K,
            const float* __restrict__ bias,   // MODE1: bias_s ; MODE2: bias_css
            const float* __restrict__ U,      // MODE2: U[t] base (B x S)
            float* __restrict__ inbuf,        // MODE2: [in_s | in_css] (B x 640)
            float* __restrict__ actout,       // MODE2: next activation buffer
            float* __restrict__ dout)         // MODE2: output slice or nullptr
{
    __shared__ float As[16][128];
    __shared__ float Bs[16][128];

    const int tid = threadIdx.x;
    const int m0 = blockIdx.y * 128;
    const int n0 = blockIdx.x * 128;

    // global->shared load mapping
    const int a_row = tid >> 2;          // 0..63 (two passes: +0, +64)
    const int a_col = (tid & 3) * 4;     // 0,4,8,12
    const int b_row = tid >> 5;          // 0..7 (two passes: +0, +8)
    const int b_col = (tid & 31) * 4;

    const int tm = (tid >> 4) * 8;       // 0..120
    const int tn = (tid & 15) * 8;       // 0..120

    float acc[8][8];
    #pragma unroll
    for (int i = 0; i < 8; i++)
        #pragma unroll
        for (int j = 0; j < 8; j++) acc[i][j] = 0.0f;

    for (int k0 = 0; k0 < K; k0 += 16) {
        #pragma unroll
        for (int p = 0; p < 2; p++) {
            int r = a_row + p * 64;
            float4 v = *(const float4*)&A[(size_t)(m0 + r) * K + k0 + a_col];
            As[a_col + 0][r] = v.x;
            As[a_col + 1][r] = v.y;
            As[a_col + 2][r] = v.z;
            As[a_col + 3][r] = v.w;
        }
        #pragma unroll
        for (int p = 0; p < 2; p++) {
            int r = b_row + p * 8;
            *(float4*)&Bs[r][b_col] =
                *(const float4*)&Bm[(size_t)(k0 + r) * N + n0 + b_col];
        }
        __syncthreads();

        #pragma unroll
        for (int k = 0; k < 16; k++) {
            float a[8], b[8];
            *(float4*)&a[0] = *(const float4*)&As[k][tm];
            *(float4*)&a[4] = *(const float4*)&As[k][tm + 4];
            *(float4*)&b[0] = *(const float4*)&Bs[k][tn];
            *(float4*)&b[4] = *(const float4*)&Bs[k][tn + 4];
            #pragma unroll
            for (int i = 0; i < 8; i++)
                #pragma unroll
                for (int j = 0; j < 8; j++)
                    acc[i][j] += a[i] * b[j];
        }
        __syncthreads();
    }

    if (MODE == 0) {
        #pragma unroll
        for (int i = 0; i < 8; i++) {
            size_t row = (size_t)(m0 + tm + i) * N + n0 + tn;
            *(float4*)&C[row + 0] = *(float4*)&acc[i][0];
            *(float4*)&C[row + 4] = *(float4*)&acc[i][4];
        }
    } else if (MODE == 1) {
        float bv[8];
        #pragma unroll
        for (int j = 0; j < 8; j++) bv[j] = bias[n0 + tn + j];
        #pragma unroll
        for (int i = 0; i < 8; i++) {
            size_t row = (size_t)(m0 + tm + i) * N + n0 + tn;
            #pragma unroll
            for (int j = 0; j < 8; j++) C[row + j] = acc[i][j] + bv[j];
        }
    } else {
        // Fused recurrent step. n0 is either entirely in the s-region (<512)
        // or entirely in the css-region (>=512) since S_DIM is tile-aligned.
        const bool is_css = (n0 >= S_DIM);
        #pragma unroll
        for (int i = 0; i < 8; i++) {
            int m = m0 + tm + i;
            size_t sidx = (size_t)m * SC_DIM + n0 + tn;
            #pragma unroll
            for (int j = 0; j < 8; j++) {
                int n = n0 + tn + j;
                float pre = acc[i][j];
                float val;
                if (!is_css) {
                    val = TAUF * (pre + U[(size_t)m * S_DIM + n]) + OMTF * inbuf[sidx + j];
                } else {
                    val = TAUF * (pre + bias[n - S_DIM]) + OMTF * inbuf[sidx + j];
                }
                inbuf[sidx + j] = val;
                float a = sigf(val);
                actout[sidx + j] = a;
                if (!is_css && dout) dout[(size_t)m * S_DIM + n] = a;
            }
        }
    }
}

// Leaky scan over t for the hps pathway; converts Z -> a_hps carries in place.
// g_hbuf[t] on exit holds a_hps used AT step t (i.e. sigmoid(in_hps[t-1]), 0.5 at t=0).
__global__ void hps_scan(const float* __restrict__ bias_hps)
{
    int idx = blockIdx.x * blockDim.x + threadIdx.x;   // over B*H
    if (idx >= B_DIM * H_DIM) return;
    float bias = bias_hps[idx % H_DIM];
    float prev = 0.0f;                                  // in_hps init
    #pragma unroll
    for (int t = 0; t < T_STEPS; t++) {
        size_t off = (size_t)t * (B_DIM * H_DIM) + idx;
        float z = g_hbuf[off];
        g_hbuf[off] = sigf(prev);                       // sig(0)=0.5 matches init act
        prev = TAUF * (z + bias) + OMTF * prev;
    }
}

__global__ void init_state()
{
    int idx = blockIdx.x * blockDim.x + threadIdx.x;   // over B*SC
    if (idx >= B_DIM * SC_DIM) return;
    g_in[idx]   = 0.0f;
    g_act0[idx] = 0.5f;
}

__global__ void build_wbig(const float* __restrict__ w_ss,
                           const float* __restrict__ w_sc,
                           const float* __restrict__ w_cs)
{
    int idx = blockIdx.x * blockDim.x + threadIdx.x;   // over 640*640
    if (idx >= SC_DIM * SC_DIM) return;
    int k = idx / SC_DIM, n = idx % SC_DIM;
    float v;
    if (k < S_DIM) v = (n < S_DIM) ? w_ss[k * S_DIM + n] : w_sc[k * C_DIM + (n - S_DIM)];
    else           v = (n < S_DIM) ? w_cs[(k - S_DIM) * S_DIM + n] : 0.0f;
    g_wbig[idx] = v;
}

extern "C" void kernel_launch(void* const* d_in, const int* in_sizes, int n_in,
                              void* d_out, int out_size)
{
    const float* x     = (const float*)d_in[0];
    const float* w_ph  = (const float*)d_in[1];
    const float* w_hs  = (const float*)d_in[2];
    const float* w_ss  = (const float*)d_in[3];
    const float* w_sc  = (const float*)d_in[4];
    const float* w_cs  = (const float*)d_in[5];
    const float* b_hps = (const float*)d_in[6];
    const float* b_s   = (const float*)d_in[7];
    const float* b_css = (const float*)d_in[8];
    float* out = (float*)d_out;

    float *hbuf, *ubuf, *act0, *act1, *inb, *wbig;
    cudaGetSymbolAddress((void**)&hbuf, g_hbuf);
    cudaGetSymbolAddress((void**)&ubuf, g_ubuf);
    cudaGetSymbolAddress((void**)&act0, g_act0);
    cudaGetSymbolAddress((void**)&act1, g_act1);
    cudaGetSymbolAddress((void**)&inb,  g_in);
    cudaGetSymbolAddress((void**)&wbig, g_wbig);

    const int MB = T_STEPS * B_DIM;   // 327680

    // 1) Z = X @ W_ph  (all timesteps at once)
    gemm_kernel<0><<<dim3(H_DIM / 128, MB / 128), 256>>>(
        x, w_ph, hbuf, MB, H_DIM, P_DIM, nullptr, nullptr, nullptr, nullptr, nullptr);

    // 2) hps leaky scan -> a_hps carries (in place)
    hps_scan<<<(B_DIM * H_DIM) / 256, 256>>>(b_hps);

    // 3) U[t] = a_hps[t] @ W_hs + bias_s  (all timesteps at once)
    gemm_kernel<1><<<dim3(S_DIM / 128, MB / 128), 256>>>(
        hbuf, w_hs, ubuf, MB, S_DIM, H_DIM, b_s, nullptr, nullptr, nullptr, nullptr);

    // 4) state init + packed recurrent weight matrix
    init_state<<<(B_DIM * SC_DIM) / 256, 256>>>();
    build_wbig<<<(SC_DIM * SC_DIM + 255) / 256, 256>>>(w_ss, w_sc, w_cs);

    // 5) sequential s/css recurrence: one fused GEMM per timestep
    for (int t = 0; t < T_STEPS; t++) {
        float* ain  = (t & 1) ? act1 : act0;
        float* aout = (t & 1) ? act0 : act1;
        float* dptr = (t >= T_STEPS - 4)
                      ? out + (size_t)(t - (T_STEPS - 4)) * B_DIM * S_DIM
                      : nullptr;
        gemm_kernel<2><<<dim3(SC_DIM / 128, B_DIM / 128), 256>>>(
            ain, wbig, nullptr, B_DIM, SC_DIM, SC_DIM,
            b_css, ubuf + (size_t)t * B_DIM * S_DIM, inb, aout, dptr);
    }
}

// round 4
// speedup vs baseline: 5.4650x; 5.4650x over previous
#include <cuda_runtime.h>
#include <cuda_fp16.h>
#include <cuda.h>
#include <math.h>
#include <stdint.h>

// ---------------- problem constants ----------------
#define T_STEPS 20
#define B_DIM   16384
#define P_DIM   256
#define H_DIM   512
#define S_DIM   512
#define C_DIM   128
#define SC_DIM  640
#define TAUF    0.25f
#define OMTF    0.75f

// ---------------- GEMM tile config ----------------
#define BM 128
#define BN 128
#define BK 64
#define NSTAGE 3
#define A_BYTES (BM * BK * 2)                 // 16384
#define B_BYTES (BN * BK * 2)                 // 16384
#define STAGE_BYTES (A_BYTES + B_BYTES)       // 32768
// hdr (mbarriers) + 1024B alignment slack + stages
#define SMEM_TOTAL (2048 + NSTAGE * STAGE_BYTES)   // 100352
#define OFF_FULL(s)  ((s) * 8)

// ---------------- device scratch (static; no runtime alloc) ----------------
__device__ __align__(256) __half g_xh  [(size_t)T_STEPS * B_DIM * P_DIM];
__device__ __align__(256) __half g_zbuf[(size_t)T_STEPS * B_DIM * H_DIM];
__device__ __align__(256) __half g_ubuf[(size_t)T_STEPS * B_DIM * S_DIM];
__device__ __align__(256) __half g_act0[(size_t)B_DIM * SC_DIM];
__device__ __align__(256) __half g_act1[(size_t)B_DIM * SC_DIM];
__device__ __align__(256) float  g_in  [(size_t)B_DIM * SC_DIM];
__device__ __align__(256) __half g_wphT [H_DIM * P_DIM];
__device__ __align__(256) __half g_whsT [S_DIM * H_DIM];
__device__ __align__(256) __half g_wbigT[SC_DIM * SC_DIM];

// ---------------- PTX helpers ----------------
__device__ __forceinline__ uint32_t smem_u32(const void* p) {
    uint32_t a;
    asm("{ .reg .u64 t; cvta.to.shared.u64 t, %1; cvt.u32.u64 %0, t; }" : "=r"(a) : "l"(p));
    return a;
}
__device__ __forceinline__ void mbar_init(uint32_t m, uint32_t cnt) {
    asm volatile("mbarrier.init.shared.b64 [%0], %1;" :: "r"(m), "r"(cnt) : "memory");
}
__device__ __forceinline__ void mbar_expect_tx(uint32_t m, uint32_t bytes) {
    asm volatile("mbarrier.arrive.expect_tx.shared.b64 _, [%0], %1;" :: "r"(m), "r"(bytes) : "memory");
}
__device__ __forceinline__ void mbar_wait(uint32_t m, uint32_t parity) {
    asm volatile(
        "{\n\t.reg .pred P;\n\t"
        "WL_%=:\n\t"
        "mbarrier.try_wait.parity.acquire.cta.shared::cta.b64 P, [%0], %1, 0x989680;\n\t"
        "@P bra.uni WD_%=;\n\t"
        "bra.uni WL_%=;\n\t"
        "WD_%=:\n\t}"
        :: "r"(m), "r"(parity) : "memory");
}
__device__ __forceinline__ void tma2d(uint32_t dst, const CUtensorMap* map, int x, int y, uint32_t mbar) {
    asm volatile(
        "cp.async.bulk.tensor.2d.shared::cta.global.tile.mbarrier::complete_tx::bytes "
        "[%0], [%1, {%2, %3}], [%4];"
        :: "r"(dst), "l"(map), "r"(x), "r"(y), "r"(mbar) : "memory");
}
__device__ __forceinline__ void ldsm4(uint32_t* r, uint32_t addr) {
    asm volatile("ldmatrix.sync.aligned.m8n8.x4.shared.b16 {%0,%1,%2,%3}, [%4];"
                 : "=r"(r[0]), "=r"(r[1]), "=r"(r[2]), "=r"(r[3]) : "r"(addr));
}
__device__ __forceinline__ void mma16816(float* c, const uint32_t* a, uint32_t b0, uint32_t b1) {
    asm volatile(
        "mma.sync.aligned.m16n8k16.row.col.f32.f16.f16.f32 "
        "{%0,%1,%2,%3}, {%4,%5,%6,%7}, {%8,%9}, {%0,%1,%2,%3};"
        : "+f"(c[0]), "+f"(c[1]), "+f"(c[2]), "+f"(c[3])
        : "r"(a[0]), "r"(a[1]), "r"(a[2]), "r"(a[3]), "r"(b0), "r"(b1));
}
__device__ __forceinline__ float sigf(float x) { return 1.0f / (1.0f + __expf(-x)); }

// ---------------------------------------------------------------------------
// fp16 tensor-core GEMM via mma.sync: D[m,n] = sum_k A[m,k] * BT[n,k]
// MODE 0: store fp16   MODE 1: store fp16 + bias_s[n]   MODE 2: recurrent epi
// 256 threads = 8 warps in 4(m) x 2(n) grid, 32x64 per warp.
// ---------------------------------------------------------------------------
template<int MODE>
__global__ void __launch_bounds__(256, 2)
tc_gemm(const __grid_constant__ CUtensorMap tma_a,
        const __grid_constant__ CUtensorMap tma_b,
        int nk,
        const float* __restrict__ bias,   // M1: bias_s ; M2: bias_css
        const __half* __restrict__ U,     // M2: U[t] (B x S) fp16
        float* __restrict__ inbuf,        // M2: fp32 carry (B x 640)
        __half* __restrict__ hout,        // M0: zbuf  M1: ubuf  M2: act out
        float* __restrict__ dout,         // M2: output slice or nullptr
        int nld)
{
    extern __shared__ char smem[];
    const uint32_t sb = smem_u32(smem);
    // SW128 swizzle is a function of absolute SMEM address bits — stage ring
    // MUST be 1024B aligned (swizzle atom = 8 rows x 128B).
    const uint32_t stage0 = (sb + 64 + 1023) & ~1023u;
    const int tid  = threadIdx.x;
    const int lane = tid & 31;
    const int w    = tid >> 5;
    const int wm   = w & 3;          // m-block 0..3 (32 rows each)
    const int wn   = w >> 2;         // n-block 0..1 (64 cols each)
    const int m0 = blockIdx.y * BM;
    const int n0 = blockIdx.x * BN;

    if (tid == 0) {
        #pragma unroll
        for (int s = 0; s < NSTAGE; s++) mbar_init(sb + OFF_FULL(s), 1);
    }
    __syncthreads();

    // prologue: prefetch up to NSTAGE stages
    if (tid == 0) {
        int pre = nk < NSTAGE ? nk : NSTAGE;
        for (int kc = 0; kc < pre; kc++) {
            uint32_t st = stage0 + kc * STAGE_BYTES;
            mbar_expect_tx(sb + OFF_FULL(kc), STAGE_BYTES);
            tma2d(st,           &tma_a, kc * BK, m0, sb + OFF_FULL(kc));
            tma2d(st + A_BYTES, &tma_b, kc * BK, n0, sb + OFF_FULL(kc));
        }
    }

    // per-thread ldmatrix address components (swizzle folded in)
    const uint32_t xr = (uint32_t)(lane & 7) * 16;          // SW128 xor (row&7)*16
    const uint32_t koff = (uint32_t)(lane >> 4) * 16;       // 16B half-select
    uint32_t aRow[2], bRow[4];
    #pragma unroll
    for (int mi = 0; mi < 2; mi++)
        aRow[mi] = (uint32_t)(wm * 32 + mi * 16 + (lane & 15)) * 128;
    #pragma unroll
    for (int nq = 0; nq < 4; nq++)
        bRow[nq] = (uint32_t)(wn * 64 + nq * 16 + (lane & 15)) * 128;

    float acc[2][8][4];
    #pragma unroll
    for (int mi = 0; mi < 2; mi++)
        #pragma unroll
        for (int ni = 0; ni < 8; ni++)
            #pragma unroll
            for (int q = 0; q < 4; q++) acc[mi][ni][q] = 0.0f;

    for (int kc = 0; kc < nk; kc++) {
        const int s = kc % NSTAGE;
        mbar_wait(sb + OFF_FULL(s), (uint32_t)((kc / NSTAGE) & 1));
        const uint32_t stA = stage0 + s * STAGE_BYTES;
        const uint32_t stB = stA + A_BYTES;

        #pragma unroll
        for (int k16 = 0; k16 < 4; k16++) {
            const uint32_t kb = (uint32_t)k16 * 32 + koff;
            uint32_t af[2][4], bf[4][4];
            #pragma unroll
            for (int mi = 0; mi < 2; mi++)
                ldsm4(af[mi], stA + aRow[mi] + (kb ^ xr));
            #pragma unroll
            for (int nq = 0; nq < 4; nq++)
                ldsm4(bf[nq], stB + bRow[nq] + (kb ^ xr));
            #pragma unroll
            for (int mi = 0; mi < 2; mi++)
                #pragma unroll
                for (int nq = 0; nq < 4; nq++) {
                    mma16816(acc[mi][nq * 2 + 0], af[mi], bf[nq][0], bf[nq][2]);
                    mma16816(acc[mi][nq * 2 + 1], af[mi], bf[nq][1], bf[nq][3]);
                }
        }
        __syncthreads();   // all warps done with stage s
        if (tid == 0 && kc + NSTAGE < nk) {
            const int kn = kc + NSTAGE;
            const int s2 = kn % NSTAGE;
            const uint32_t st = stage0 + s2 * STAGE_BYTES;
            mbar_expect_tx(sb + OFF_FULL(s2), STAGE_BYTES);
            tma2d(st,           &tma_a, kn * BK, m0, sb + OFF_FULL(s2));
            tma2d(st + A_BYTES, &tma_b, kn * BK, n0, sb + OFF_FULL(s2));
        }
    }

    // ---------------- epilogue (registers -> global) ----------------
    const int rbase = lane >> 2;          // 0..7
    const int cpair = (lane & 3) * 2;     // 0,2,4,6
    const bool css = (MODE == 2) && (n0 >= S_DIM);

    #pragma unroll
    for (int mi = 0; mi < 2; mi++) {
        #pragma unroll
        for (int h = 0; h < 2; h++) {
            const int m = m0 + wm * 32 + mi * 16 + rbase + h * 8;
            #pragma unroll
            for (int ni = 0; ni < 8; ni++) {
                const int n = n0 + wn * 64 + ni * 8 + cpair;
                const float c0 = acc[mi][ni][h * 2 + 0];
                const float c1 = acc[mi][ni][h * 2 + 1];
                if (MODE == 0) {
                    *(__half2*)(hout + (size_t)m * nld + n) = __floats2half2_rn(c0, c1);
                } else if (MODE == 1) {
                    *(__half2*)(hout + (size_t)m * nld + n) =
                        __floats2half2_rn(c0 + bias[n], c1 + bias[n + 1]);
                } else {
                    const size_t ib = (size_t)m * SC_DIM + n;
                    float2 iv = *(const float2*)(inbuf + ib);
                    float v0, v1;
                    if (!css) {
                        const __half2 uh = *(const __half2*)(U + (size_t)m * S_DIM + n);
                        const float2 uf = __half22float2(uh);
                        v0 = TAUF * (c0 + uf.x) + OMTF * iv.x;
                        v1 = TAUF * (c1 + uf.y) + OMTF * iv.y;
                    } else {
                        v0 = TAUF * (c0 + bias[n - S_DIM])     + OMTF * iv.x;
                        v1 = TAUF * (c1 + bias[n - S_DIM + 1]) + OMTF * iv.y;
                    }
                    *(float2*)(inbuf + ib) = make_float2(v0, v1);
                    const float a0 = sigf(v0), a1 = sigf(v1);
                    *(__half2*)(hout + ib) = __floats2half2_rn(a0, a1);
                    if (!css && dout)
                        *(float2*)(dout + (size_t)m * S_DIM + n) = make_float2(a0, a1);
                }
            }
        }
    }
}

// ---------------- small helper kernels ----------------
__global__ void conv_x(const float* __restrict__ x) {
    size_t i = (size_t)blockIdx.x * blockDim.x + threadIdx.x;
    size_t n4 = (size_t)T_STEPS * B_DIM * P_DIM / 4;
    if (i >= n4) return;
    float4 v = ((const float4*)x)[i];
    __half2* o = (__half2*)g_xh;
    o[2 * i]     = __floats2half2_rn(v.x, v.y);
    o[2 * i + 1] = __floats2half2_rn(v.z, v.w);
}

__global__ void hps_scan(const float* __restrict__ bias_hps) {
    int idx = blockIdx.x * blockDim.x + threadIdx.x;
    if (idx >= B_DIM * H_DIM) return;
    float b = bias_hps[idx % H_DIM];
    float prev = 0.0f;
    #pragma unroll
    for (int t = 0; t < T_STEPS; t++) {
        size_t off = (size_t)t * (B_DIM * H_DIM) + idx;
        float z = __half2float(g_zbuf[off]);
        g_zbuf[off] = __float2half_rn(sigf(prev));
        prev = TAUF * (z + b) + OMTF * prev;
    }
}

__global__ void init_state() {
    int idx = blockIdx.x * blockDim.x + threadIdx.x;
    if (idx >= B_DIM * SC_DIM) return;
    g_in[idx] = 0.0f;
    g_act0[idx] = __float2half_rn(0.5f);
}

__global__ void prep_wph(const float* __restrict__ w) {
    int i = blockIdx.x * blockDim.x + threadIdx.x;
    if (i >= H_DIM * P_DIM) return;
    int n = i / P_DIM, k = i % P_DIM;
    g_wphT[i] = __float2half_rn(w[k * H_DIM + n]);
}
__global__ void prep_whs(const float* __restrict__ w) {
    int i = blockIdx.x * blockDim.x + threadIdx.x;
    if (i >= S_DIM * H_DIM) return;
    int n = i / H_DIM, k = i % H_DIM;
    g_whsT[i] = __float2half_rn(w[k * S_DIM + n]);
}
__global__ void prep_wbig(const float* __restrict__ w_ss,
                          const float* __restrict__ w_sc,
                          const float* __restrict__ w_cs) {
    int i = blockIdx.x * blockDim.x + threadIdx.x;
    if (i >= SC_DIM * SC_DIM) return;
    int n = i / SC_DIM, k = i % SC_DIM;
    float v;
    if (n < S_DIM) v = (k < S_DIM) ? w_ss[k * S_DIM + n] : w_cs[(k - S_DIM) * S_DIM + n];
    else           v = (k < S_DIM) ? w_sc[k * C_DIM + (n - S_DIM)] : 0.0f;
    g_wbigT[i] = __float2half_rn(v);
}

// ---------------- host side ----------------
typedef CUresult (*PFN_tmapEncode)(
    CUtensorMap*, CUtensorMapDataType, cuuint32_t, void*,
    const cuuint64_t*, const cuuint64_t*, const cuuint32_t*, const cuuint32_t*,
    CUtensorMapInterleave, CUtensorMapSwizzle, CUtensorMapL2promotion,
    CUtensorMapFloatOOBfill);

static void make_map2d(PFN_tmapEncode fn, CUtensorMap* m, void* ptr,
                       uint64_t K, uint64_t M) {
    cuuint64_t dims[2]    = {K, M};
    cuuint64_t strides[1] = {K * 2};
    cuuint32_t box[2]     = {BK, BM};
    cuuint32_t es[2]      = {1, 1};
    fn(m, CU_TENSOR_MAP_DATA_TYPE_FLOAT16, 2, ptr, dims, strides, box, es,
       CU_TENSOR_MAP_INTERLEAVE_NONE, CU_TENSOR_MAP_SWIZZLE_128B,
       CU_TENSOR_MAP_L2_PROMOTION_L2_128B, CU_TENSOR_MAP_FLOAT_OOB_FILL_NONE);
}

extern "C" void kernel_launch(void* const* d_in, const int* in_sizes, int n_in,
                              void* d_out, int out_size)
{
    const float* x     = (const float*)d_in[0];
    const float* w_ph  = (const float*)d_in[1];
    const float* w_hs  = (const float*)d_in[2];
    const float* w_ss  = (const float*)d_in[3];
    const float* w_sc  = (const float*)d_in[4];
    const float* w_cs  = (const float*)d_in[5];
    const float* b_hps = (const float*)d_in[6];
    const float* b_s   = (const float*)d_in[7];
    const float* b_css = (const float*)d_in[8];
    float* out = (float*)d_out;

    void *xh, *zbuf, *ubuf, *act0, *act1, *inb, *wphT, *whsT, *wbigT;
    cudaGetSymbolAddress(&xh, g_xh);
    cudaGetSymbolAddress(&zbuf, g_zbuf);
    cudaGetSymbolAddress(&ubuf, g_ubuf);
    cudaGetSymbolAddress(&act0, g_act0);
    cudaGetSymbolAddress(&act1, g_act1);
    cudaGetSymbolAddress(&inb, g_in);
    cudaGetSymbolAddress(&wphT, g_wphT);
    cudaGetSymbolAddress(&whsT, g_whsT);
    cudaGetSymbolAddress(&wbigT, g_wbigT);

    PFN_tmapEncode encode = nullptr;
    cudaDriverEntryPointQueryResult qr;
    cudaGetDriverEntryPointByVersion("cuTensorMapEncodeTiled", (void**)&encode,
                                     12000, cudaEnableDefault, &qr);

    const uint64_t MB = (uint64_t)T_STEPS * B_DIM;   // 327680

    CUtensorMap m_xh, m_wph, m_z, m_whs, m_a0, m_a1, m_wbig;
    make_map2d(encode, &m_xh,  xh,    P_DIM,  MB);
    make_map2d(encode, &m_wph, wphT,  P_DIM,  H_DIM);
    make_map2d(encode, &m_z,   zbuf,  H_DIM,  MB);
    make_map2d(encode, &m_whs, whsT,  H_DIM,  S_DIM);
    make_map2d(encode, &m_a0,  act0,  SC_DIM, B_DIM);
    make_map2d(encode, &m_a1,  act1,  SC_DIM, B_DIM);
    make_map2d(encode, &m_wbig, wbigT, SC_DIM, SC_DIM);

    cudaFuncSetAttribute(tc_gemm<0>, cudaFuncAttributeMaxDynamicSharedMemorySize, SMEM_TOTAL);
    cudaFuncSetAttribute(tc_gemm<1>, cudaFuncAttributeMaxDynamicSharedMemorySize, SMEM_TOTAL);
    cudaFuncSetAttribute(tc_gemm<2>, cudaFuncAttributeMaxDynamicSharedMemorySize, SMEM_TOTAL);

    // 0) conversions / preps
    conv_x<<<(unsigned)((MB * P_DIM / 4 + 255) / 256), 256>>>(x);
    prep_wph<<<(H_DIM * P_DIM + 255) / 256, 256>>>(w_ph);
    prep_whs<<<(S_DIM * H_DIM + 255) / 256, 256>>>(w_hs);
    prep_wbig<<<(SC_DIM * SC_DIM + 255) / 256, 256>>>(w_ss, w_sc, w_cs);
    init_state<<<(B_DIM * SC_DIM + 255) / 256, 256>>>();

    // 1) Z = Xh @ WphT^T   (M=327680, N=512, K=256)
    tc_gemm<0><<<dim3(H_DIM / BN, (unsigned)(MB / BM)), 256, SMEM_TOTAL>>>(
        m_xh, m_wph, P_DIM / BK, nullptr, nullptr, nullptr,
        (__half*)zbuf, nullptr, H_DIM);

    // 2) hps scan
    hps_scan<<<(B_DIM * H_DIM) / 256, 256>>>(b_hps);

    // 3) U = a_hps @ WhsT^T + bias_s  (K=512)
    tc_gemm<1><<<dim3(S_DIM / BN, (unsigned)(MB / BM)), 256, SMEM_TOTAL>>>(
        m_z, m_whs, H_DIM / BK, b_s, nullptr, nullptr,
        (__half*)ubuf, nullptr, S_DIM);

    // 4) sequential recurrence
    for (int t = 0; t < T_STEPS; t++) {
        const CUtensorMap& ma = (t & 1) ? m_a1 : m_a0;
        __half* aout = (__half*)((t & 1) ? act0 : act1);
        float* dptr = (t >= T_STEPS - 4)
                      ? out + (size_t)(t - (T_STEPS - 4)) * B_DIM * S_DIM
                      : nullptr;
        tc_gemm<2><<<dim3(SC_DIM / BN, B_DIM / BM), 256, SMEM_TOTAL>>>(
            ma, m_wbig, SC_DIM / BK, b_css,
            (const __half*)ubuf + (size_t)t * B_DIM * S_DIM,
            (float*)inb, aout, dptr, SC_DIM);
    }
}

// round 5
// speedup vs baseline: 6.1233x; 1.1205x over previous
#include <cuda_runtime.h>
#include <cuda_fp16.h>
#include <cuda.h>
#include <math.h>
#include <stdint.h>

// ---------------- problem constants ----------------
#define T_STEPS 20
#define B_DIM   16384
#define P_DIM   256
#define H_DIM   512
#define S_DIM   512
#define C_DIM   128
#define SC_DIM  640
#define TAUF    0.25f
#define OMTF    0.75f

// ---------------- GEMM tile config (shared by both kernels) ----------------
#define BM 128
#define BN 128
#define BK 64
#define NSTAGE 3
#define A_BYTES (BM * BK * 2)                 // 16384
#define B_BYTES (BN * BK * 2)                 // 16384
#define STAGE_BYTES (A_BYTES + B_BYTES)       // 32768
#define SMEM_TOTAL (2048 + NSTAGE * STAGE_BYTES)   // 100352 (stage ring 1024B-aligned inside)
#define OFF_FULL(s)  ((s) * 8)

// recurrent persistent kernel
#define R_TILES_M   (B_DIM / BM)      // 128
#define R_TILES_N   (SC_DIM / BN)     // 5
#define R_TILES     (R_TILES_M * R_TILES_N)          // 640
#define R_TOTAL     (T_STEPS * R_TILES)              // 12800
#define R_NK        (SC_DIM / BK)     // 10
#define R_GRID      296               // 2 CTAs per SM, all co-resident

// ---------------- device scratch (static; no runtime alloc) ----------------
__device__ __align__(256) __half g_xh  [(size_t)T_STEPS * B_DIM * P_DIM];
__device__ __align__(256) __half g_zbuf[(size_t)T_STEPS * B_DIM * H_DIM];
__device__ __align__(256) __half g_ubuf[(size_t)T_STEPS * B_DIM * S_DIM];
__device__ __align__(256) __half g_act0[(size_t)B_DIM * SC_DIM];
__device__ __align__(256) __half g_act1[(size_t)B_DIM * SC_DIM];
__device__ __align__(256) float  g_in  [(size_t)B_DIM * SC_DIM];
__device__ __align__(256) __half g_wphT [H_DIM * P_DIM];
__device__ __align__(256) __half g_whsT [S_DIM * H_DIM];
__device__ __align__(256) __half g_wbigT[SC_DIM * SC_DIM];
__device__ unsigned g_ready[T_STEPS * R_TILES_M];   // per (t, m-block) completion count
__device__ unsigned g_counter;                      // work counter

// ---------------- PTX helpers ----------------
__device__ __forceinline__ uint32_t smem_u32(const void* p) {
    uint32_t a;
    asm("{ .reg .u64 t; cvta.to.shared.u64 t, %1; cvt.u32.u64 %0, t; }" : "=r"(a) : "l"(p));
    return a;
}
__device__ __forceinline__ void mbar_init(uint32_t m, uint32_t cnt) {
    asm volatile("mbarrier.init.shared.b64 [%0], %1;" :: "r"(m), "r"(cnt) : "memory");
}
__device__ __forceinline__ void mbar_expect_tx(uint32_t m, uint32_t bytes) {
    asm volatile("mbarrier.arrive.expect_tx.shared.b64 _, [%0], %1;" :: "r"(m), "r"(bytes) : "memory");
}
__device__ __forceinline__ void mbar_wait(uint32_t m, uint32_t parity) {
    asm volatile(
        "{\n\t.reg .pred P;\n\t"
        "WL_%=:\n\t"
        "mbarrier.try_wait.parity.acquire.cta.shared::cta.b64 P, [%0], %1, 0x989680;\n\t"
        "@P bra.uni WD_%=;\n\t"
        "bra.uni WL_%=;\n\t"
        "WD_%=:\n\t}"
        :: "r"(m), "r"(parity) : "memory");
}
__device__ __forceinline__ void tma2d(uint32_t dst, const CUtensorMap* map, int x, int y, uint32_t mbar) {
    asm volatile(
        "cp.async.bulk.tensor.2d.shared::cta.global.tile.mbarrier::complete_tx::bytes "
        "[%0], [%1, {%2, %3}], [%4];"
        :: "r"(dst), "l"(map), "r"(x), "r"(y), "r"(mbar) : "memory");
}
__device__ __forceinline__ void ldsm4(uint32_t* r, uint32_t addr) {
    asm volatile("ldmatrix.sync.aligned.m8n8.x4.shared.b16 {%0,%1,%2,%3}, [%4];"
                 : "=r"(r[0]), "=r"(r[1]), "=r"(r[2]), "=r"(r[3]) : "r"(addr));
}
__device__ __forceinline__ void mma16816(float* c, const uint32_t* a, uint32_t b0, uint32_t b1) {
    asm volatile(
        "mma.sync.aligned.m16n8k16.row.col.f32.f16.f16.f32 "
        "{%0,%1,%2,%3}, {%4,%5,%6,%7}, {%8,%9}, {%0,%1,%2,%3};"
        : "+f"(c[0]), "+f"(c[1]), "+f"(c[2]), "+f"(c[3])
        : "r"(a[0]), "r"(a[1]), "r"(a[2]), "r"(a[3]), "r"(b0), "r"(b1));
}
__device__ __forceinline__ void cpa16(uint32_t dst, const void* src) {
    asm volatile("cp.async.cg.shared.global [%0], [%1], 16;" :: "r"(dst), "l"(src));
}
__device__ __forceinline__ void cpa_commit() { asm volatile("cp.async.commit_group;" ::: "memory"); }
template<int N> __device__ __forceinline__ void cpa_wait() {
    asm volatile("cp.async.wait_group %0;" :: "n"(N) : "memory");
}
__device__ __forceinline__ float sigf(float x) { return 1.0f / (1.0f + __expf(-x)); }

// ---------------------------------------------------------------------------
// TMA-fed fp16 GEMM for the big parallel matmuls.
// MODE 0: store fp16     MODE 1: store fp16 + bias[n]
// ---------------------------------------------------------------------------
template<int MODE>
__global__ void __launch_bounds__(256, 2)
tc_gemm(const __grid_constant__ CUtensorMap tma_a,
        const __grid_constant__ CUtensorMap tma_b,
        int nk,
        const float* __restrict__ bias,
        __half* __restrict__ hout,
        int nld)
{
    extern __shared__ char smem[];
    const uint32_t sb = smem_u32(smem);
    const uint32_t stage0 = (sb + 64 + 1023) & ~1023u;   // SW128 needs 1024B alignment
    const int tid  = threadIdx.x;
    const int lane = tid & 31;
    const int w    = tid >> 5;
    const int wm   = w & 3;
    const int wn   = w >> 2;
    const int m0 = blockIdx.y * BM;
    const int n0 = blockIdx.x * BN;

    if (tid == 0) {
        #pragma unroll
        for (int s = 0; s < NSTAGE; s++) mbar_init(sb + OFF_FULL(s), 1);
    }
    __syncthreads();

    if (tid == 0) {
        int pre = nk < NSTAGE ? nk : NSTAGE;
        for (int kc = 0; kc < pre; kc++) {
            uint32_t st = stage0 + kc * STAGE_BYTES;
            mbar_expect_tx(sb + OFF_FULL(kc), STAGE_BYTES);
            tma2d(st,           &tma_a, kc * BK, m0, sb + OFF_FULL(kc));
            tma2d(st + A_BYTES, &tma_b, kc * BK, n0, sb + OFF_FULL(kc));
        }
    }

    const uint32_t xr   = (uint32_t)(lane & 7) * 16;
    const uint32_t koff = (uint32_t)(lane >> 4) * 16;
    uint32_t aRow[2], bRow[4];
    #pragma unroll
    for (int mi = 0; mi < 2; mi++)
        aRow[mi] = (uint32_t)(wm * 32 + mi * 16 + (lane & 15)) * 128;
    #pragma unroll
    for (int nq = 0; nq < 4; nq++)
        bRow[nq] = (uint32_t)(wn * 64 + nq * 16 + (lane & 15)) * 128;

    float acc[2][8][4];
    #pragma unroll
    for (int mi = 0; mi < 2; mi++)
        #pragma unroll
        for (int ni = 0; ni < 8; ni++)
            #pragma unroll
            for (int q = 0; q < 4; q++) acc[mi][ni][q] = 0.0f;

    for (int kc = 0; kc < nk; kc++) {
        const int s = kc % NSTAGE;
        mbar_wait(sb + OFF_FULL(s), (uint32_t)((kc / NSTAGE) & 1));
        const uint32_t stA = stage0 + s * STAGE_BYTES;
        const uint32_t stB = stA + A_BYTES;

        #pragma unroll
        for (int k16 = 0; k16 < 4; k16++) {
            const uint32_t kb = (uint32_t)k16 * 32 + koff;
            uint32_t af[2][4], bf[4][4];
            #pragma unroll
            for (int mi = 0; mi < 2; mi++)
                ldsm4(af[mi], stA + aRow[mi] + (kb ^ xr));
            #pragma unroll
            for (int nq = 0; nq < 4; nq++)
                ldsm4(bf[nq], stB + bRow[nq] + (kb ^ xr));
            #pragma unroll
            for (int mi = 0; mi < 2; mi++)
                #pragma unroll
                for (int nq = 0; nq < 4; nq++) {
                    mma16816(acc[mi][nq * 2 + 0], af[mi], bf[nq][0], bf[nq][2]);
                    mma16816(acc[mi][nq * 2 + 1], af[mi], bf[nq][1], bf[nq][3]);
                }
        }
        __syncthreads();
        if (tid == 0 && kc + NSTAGE < nk) {
            const int kn = kc + NSTAGE;
            const int s2 = kn % NSTAGE;
            const uint32_t st = stage0 + s2 * STAGE_BYTES;
            mbar_expect_tx(sb + OFF_FULL(s2), STAGE_BYTES);
            tma2d(st,           &tma_a, kn * BK, m0, sb + OFF_FULL(s2));
            tma2d(st + A_BYTES, &tma_b, kn * BK, n0, sb + OFF_FULL(s2));
        }
    }

    const int rbase = lane >> 2;
    const int cpair = (lane & 3) * 2;
    #pragma unroll
    for (int mi = 0; mi < 2; mi++) {
        #pragma unroll
        for (int h = 0; h < 2; h++) {
            const int m = m0 + wm * 32 + mi * 16 + rbase + h * 8;
            #pragma unroll
            for (int ni = 0; ni < 8; ni++) {
                const int n = n0 + wn * 64 + ni * 8 + cpair;
                const float c0 = acc[mi][ni][h * 2 + 0];
                const float c1 = acc[mi][ni][h * 2 + 1];
                if (MODE == 0) {
                    *(__half2*)(hout + (size_t)m * nld + n) = __floats2half2_rn(c0, c1);
                } else {
                    *(__half2*)(hout + (size_t)m * nld + n) =
                        __floats2half2_rn(c0 + bias[n], c1 + bias[n + 1]);
                }
            }
        }
    }
}

// ---------------------------------------------------------------------------
// Persistent recurrent kernel: all 20 timesteps of the s/css recurrence in one
// launch. Work = (t, m, n) tiles dispensed by a global counter in lex order.
// Dependency: tile (t,m,n) needs ready[t-1][m] == 5 (all n-tiles of row-block
// m at step t-1 done: their epilogue wrote act AND their mainloop finished
// reading the act buffer this tile will overwrite).
// A (activations) and B (wbig) are loaded via cp.async into SW128 layout.
// ---------------------------------------------------------------------------
__global__ void __launch_bounds__(256, 2)
rec_persist(const float* __restrict__ bias_css, float* __restrict__ out)
{
    extern __shared__ char smem[];
    unsigned* sg = (unsigned*)smem;                       // tile-id broadcast
    const uint32_t sb = smem_u32(smem);
    const uint32_t stage0 = (sb + 16 + 1023) & ~1023u;
    const int tid  = threadIdx.x;
    const int lane = tid & 31;
    const int w    = tid >> 5;
    const int wm   = w & 3;
    const int wn   = w >> 2;

    // cp.async per-thread mapping: 1024 16B-chunks per operand, 4 per thread.
    // chunk i: row r=i>>3, col16 c=i&7 ; dst = r*128 + ((c ^ (r&7))*16)
    uint32_t dstOff[4];
    int rIdx[4], cIdx[4];
    #pragma unroll
    for (int p = 0; p < 4; p++) {
        int i = tid + p * 256;
        int r = i >> 3, c = i & 7;
        rIdx[p] = r; cIdx[p] = c;
        dstOff[p] = (uint32_t)r * 128 + (uint32_t)((c ^ (r & 7)) * 16);
    }

    const uint32_t xr   = (uint32_t)(lane & 7) * 16;
    const uint32_t koff = (uint32_t)(lane >> 4) * 16;
    uint32_t aRow[2], bRow[4];
    #pragma unroll
    for (int mi = 0; mi < 2; mi++)
        aRow[mi] = (uint32_t)(wm * 32 + mi * 16 + (lane & 15)) * 128;
    #pragma unroll
    for (int nq = 0; nq < 4; nq++)
        bRow[nq] = (uint32_t)(wn * 64 + nq * 16 + (lane & 15)) * 128;

    while (true) {
        if (tid == 0) sg[0] = atomicAdd(&g_counter, 1u);
        __syncthreads();
        const unsigned g = sg[0];
        if (g >= (unsigned)R_TOTAL) break;

        const int t  = (int)(g / R_TILES);
        const int rm = (int)(g % R_TILES);
        const int m  = rm / R_TILES_N;
        const int nn = rm % R_TILES_N;
        const int m0 = m * BM;
        const int n0 = nn * BN;

        // dependency gate
        if (t > 0) {
            if (tid == 0) {
                while (*(volatile unsigned*)&g_ready[(t - 1) * R_TILES_M + m] < (unsigned)R_TILES_N)
                    __nanosleep(64);
                __threadfence();
            }
        }
        __syncthreads();   // also protects sg[0] reuse

        const __half* Aact = (t & 1) ? g_act1 : g_act0;
        __half*       Aout = (t & 1) ? g_act0 : g_act1;

        // prologue: 3 stages of cp.async
        #pragma unroll
        for (int s = 0; s < NSTAGE; s++) {
            const uint32_t st = stage0 + s * STAGE_BYTES;
            #pragma unroll
            for (int p = 0; p < 4; p++)
                cpa16(st + dstOff[p],
                      Aact + (size_t)(m0 + rIdx[p]) * SC_DIM + s * BK + cIdx[p] * 8);
            #pragma unroll
            for (int p = 0; p < 4; p++)
                cpa16(st + A_BYTES + dstOff[p],
                      g_wbigT + (size_t)(n0 + rIdx[p]) * SC_DIM + s * BK + cIdx[p] * 8);
            cpa_commit();
        }

        float acc[2][8][4];
        #pragma unroll
        for (int mi = 0; mi < 2; mi++)
            #pragma unroll
            for (int ni = 0; ni < 8; ni++)
                #pragma unroll
                for (int q = 0; q < 4; q++) acc[mi][ni][q] = 0.0f;

        #pragma unroll 1
        for (int kc = 0; kc < R_NK; kc++) {
            if (kc <= R_NK - 3)      cpa_wait<NSTAGE - 1>();
            else if (kc == R_NK - 2) cpa_wait<1>();
            else                     cpa_wait<0>();
            __syncthreads();

            const int s = kc % NSTAGE;
            const uint32_t stA = stage0 + s * STAGE_BYTES;
            const uint32_t stB = stA + A_BYTES;

            #pragma unroll
            for (int k16 = 0; k16 < 4; k16++) {
                const uint32_t kb = (uint32_t)k16 * 32 + koff;
                uint32_t af[2][4], bf[4][4];
                #pragma unroll
                for (int mi = 0; mi < 2; mi++)
                    ldsm4(af[mi], stA + aRow[mi] + (kb ^ xr));
                #pragma unroll
                for (int nq = 0; nq < 4; nq++)
                    ldsm4(bf[nq], stB + bRow[nq] + (kb ^ xr));
                #pragma unroll
                for (int mi = 0; mi < 2; mi++)
                    #pragma unroll
                    for (int nq = 0; nq < 4; nq++) {
                        mma16816(acc[mi][nq * 2 + 0], af[mi], bf[nq][0], bf[nq][2]);
                        mma16816(acc[mi][nq * 2 + 1], af[mi], bf[nq][1], bf[nq][3]);
                    }
            }
            __syncthreads();
            if (kc + NSTAGE < R_NK) {
                const int kn = kc + NSTAGE;
                const uint32_t st = stage0 + (kn % NSTAGE) * STAGE_BYTES;
                #pragma unroll
                for (int p = 0; p < 4; p++)
                    cpa16(st + dstOff[p],
                          Aact + (size_t)(m0 + rIdx[p]) * SC_DIM + kn * BK + cIdx[p] * 8);
                #pragma unroll
                for (int p = 0; p < 4; p++)
                    cpa16(st + A_BYTES + dstOff[p],
                          g_wbigT + (size_t)(n0 + rIdx[p]) * SC_DIM + kn * BK + cIdx[p] * 8);
                cpa_commit();
            }
        }

        // ---------------- fused leaky-integrator epilogue ----------------
        const bool css = (n0 >= S_DIM);
        const __half* U = g_ubuf + (size_t)t * B_DIM * S_DIM;
        float* dptr = (t >= T_STEPS - 4)
                      ? out + (size_t)(t - (T_STEPS - 4)) * B_DIM * S_DIM
                      : nullptr;
        const int rbase = lane >> 2;
        const int cpair = (lane & 3) * 2;

        #pragma unroll
        for (int mi = 0; mi < 2; mi++) {
            #pragma unroll
            for (int h = 0; h < 2; h++) {
                const int mr = m0 + wm * 32 + mi * 16 + rbase + h * 8;
                #pragma unroll
                for (int ni = 0; ni < 8; ni++) {
                    const int n = n0 + wn * 64 + ni * 8 + cpair;
                    const float c0 = acc[mi][ni][h * 2 + 0];
                    const float c1 = acc[mi][ni][h * 2 + 1];
                    const size_t ib = (size_t)mr * SC_DIM + n;
                    float2 iv = *(const float2*)(g_in + ib);
                    float v0, v1;
                    if (!css) {
                        const float2 uf = __half22float2(*(const __half2*)(U + (size_t)mr * S_DIM + n));
                        v0 = TAUF * (c0 + uf.x) + OMTF * iv.x;
                        v1 = TAUF * (c1 + uf.y) + OMTF * iv.y;
                    } else {
                        v0 = TAUF * (c0 + bias_css[n - S_DIM])     + OMTF * iv.x;
                        v1 = TAUF * (c1 + bias_css[n - S_DIM + 1]) + OMTF * iv.y;
                    }
                    *(float2*)(g_in + ib) = make_float2(v0, v1);
                    const float a0 = sigf(v0), a1 = sigf(v1);
                    *(__half2*)(Aout + ib) = __floats2half2_rn(a0, a1);
                    if (!css && dptr)
                        *(float2*)(dptr + (size_t)mr * S_DIM + n) = make_float2(a0, a1);
                }
            }
        }

        __threadfence();
        __syncthreads();
        if (tid == 0) atomicAdd(&g_ready[t * R_TILES_M + m], 1u);
    }
}

// ---------------- small helper kernels ----------------
__global__ void conv_x(const float* __restrict__ x) {
    size_t i = (size_t)blockIdx.x * blockDim.x + threadIdx.x;
    size_t n4 = (size_t)T_STEPS * B_DIM * P_DIM / 4;
    if (i >= n4) return;
    float4 v = ((const float4*)x)[i];
    __half2* o = (__half2*)g_xh;
    o[2 * i]     = __floats2half2_rn(v.x, v.y);
    o[2 * i + 1] = __floats2half2_rn(v.z, v.w);
}

__global__ void hps_scan(const float* __restrict__ bias_hps) {
    int idx = blockIdx.x * blockDim.x + threadIdx.x;
    if (idx >= B_DIM * H_DIM) return;
    float b = bias_hps[idx % H_DIM];
    float prev = 0.0f;
    #pragma unroll
    for (int t = 0; t < T_STEPS; t++) {
        size_t off = (size_t)t * (B_DIM * H_DIM) + idx;
        float z = __half2float(g_zbuf[off]);
        g_zbuf[off] = __float2half_rn(sigf(prev));
        prev = TAUF * (z + b) + OMTF * prev;
    }
}

__global__ void init_state() {
    int idx = blockIdx.x * blockDim.x + threadIdx.x;
    if (idx >= B_DIM * SC_DIM) return;
    g_in[idx] = 0.0f;
    g_act0[idx] = __float2half_rn(0.5f);
    if (idx < T_STEPS * R_TILES_M) g_ready[idx] = 0u;
    if (idx == 0) g_counter = 0u;
}

__global__ void prep_wph(const float* __restrict__ w) {
    int i = blockIdx.x * blockDim.x + threadIdx.x;
    if (i >= H_DIM * P_DIM) return;
    int n = i / P_DIM, k = i % P_DIM;
    g_wphT[i] = __float2half_rn(w[k * H_DIM + n]);
}
__global__ void prep_whs(const float* __restrict__ w) {
    int i = blockIdx.x * blockDim.x + threadIdx.x;
    if (i >= S_DIM * H_DIM) return;
    int n = i / H_DIM, k = i % H_DIM;
    g_whsT[i] = __float2half_rn(w[k * S_DIM + n]);
}
__global__ void prep_wbig(const float* __restrict__ w_ss,
                          const float* __restrict__ w_sc,
                          const float* __restrict__ w_cs) {
    int i = blockIdx.x * blockDim.x + threadIdx.x;
    if (i >= SC_DIM * SC_DIM) return;
    int n = i / SC_DIM, k = i % SC_DIM;
    float v;
    if (n < S_DIM) v = (k < S_DIM) ? w_ss[k * S_DIM + n] : w_cs[(k - S_DIM) * S_DIM + n];
    else           v = (k < S_DIM) ? w_sc[k * C_DIM + (n - S_DIM)] : 0.0f;
    g_wbigT[i] = __float2half_rn(v);
}

// ---------------- host side ----------------
typedef CUresult (*PFN_tmapEncode)(
    CUtensorMap*, CUtensorMapDataType, cuuint32_t, void*,
    const cuuint64_t*, const cuuint64_t*, const cuuint32_t*, const cuuint32_t*,
    CUtensorMapInterleave, CUtensorMapSwizzle, CUtensorMapL2promotion,
    CUtensorMapFloatOOBfill);

static void make_map2d(PFN_tmapEncode fn, CUtensorMap* m, void* ptr,
                       uint64_t K, uint64_t M) {
    cuuint64_t dims[2]    = {K, M};
    cuuint64_t strides[1] = {K * 2};
    cuuint32_t box[2]     = {BK, BM};
    cuuint32_t es[2]      = {1, 1};
    fn(m, CU_TENSOR_MAP_DATA_TYPE_FLOAT16, 2, ptr, dims, strides, box, es,
       CU_TENSOR_MAP_INTERLEAVE_NONE, CU_TENSOR_MAP_SWIZZLE_128B,
       CU_TENSOR_MAP_L2_PROMOTION_L2_128B, CU_TENSOR_MAP_FLOAT_OOB_FILL_NONE);
}

extern "C" void kernel_launch(void* const* d_in, const int* in_sizes, int n_in,
                              void* d_out, int out_size)
{
    const float* x     = (const float*)d_in[0];
    const float* w_ph  = (const float*)d_in[1];
    const float* w_hs  = (const float*)d_in[2];
    const float* w_ss  = (const float*)d_in[3];
    const float* w_sc  = (const float*)d_in[4];
    const float* w_cs  = (const float*)d_in[5];
    const float* b_hps = (const float*)d_in[6];
    const float* b_s   = (const float*)d_in[7];
    const float* b_css = (const float*)d_in[8];
    float* out = (float*)d_out;

    void *xh, *zbuf, *ubuf;
    cudaGetSymbolAddress(&xh, g_xh);
    cudaGetSymbolAddress(&zbuf, g_zbuf);
    cudaGetSymbolAddress(&ubuf, g_ubuf);

    PFN_tmapEncode encode = nullptr;
    cudaDriverEntryPointQueryResult qr;
    cudaGetDriverEntryPointByVersion("cuTensorMapEncodeTiled", (void**)&encode,
                                     12000, cudaEnableDefault, &qr);

    const uint64_t MB = (uint64_t)T_STEPS * B_DIM;   // 327680

    CUtensorMap m_xh, m_wph, m_z, m_whs;
    make_map2d(encode, &m_xh,  xh,   P_DIM, MB);
    make_map2d(encode, &m_wph, (void*)0, P_DIM, H_DIM);   // placeholder, fixed below
    // need device addresses of the weight symbols:
    void *wphT, *whsT;
    cudaGetSymbolAddress(&wphT, g_wphT);
    cudaGetSymbolAddress(&whsT, g_whsT);
    make_map2d(encode, &m_wph, wphT, P_DIM, H_DIM);
    make_map2d(encode, &m_z,   zbuf, H_DIM, MB);
    make_map2d(encode, &m_whs, whsT, H_DIM, S_DIM);

    cudaFuncSetAttribute(tc_gemm<0>, cudaFuncAttributeMaxDynamicSharedMemorySize, SMEM_TOTAL);
    cudaFuncSetAttribute(tc_gemm<1>, cudaFuncAttributeMaxDynamicSharedMemorySize, SMEM_TOTAL);
    cudaFuncSetAttribute(rec_persist, cudaFuncAttributeMaxDynamicSharedMemorySize, SMEM_TOTAL);

    // 0) conversions / preps / state+flag init
    conv_x<<<(unsigned)((MB * P_DIM / 4 + 255) / 256), 256>>>(x);
    prep_wph<<<(H_DIM * P_DIM + 255) / 256, 256>>>(w_ph);
    prep_whs<<<(S_DIM * H_DIM + 255) / 256, 256>>>(w_hs);
    prep_wbig<<<(SC_DIM * SC_DIM + 255) / 256, 256>>>(w_ss, w_sc, w_cs);
    init_state<<<(B_DIM * SC_DIM + 255) / 256, 256>>>();

    // 1) Z = Xh @ WphT^T   (M=327680, N=512, K=256)
    tc_gemm<0><<<dim3(H_DIM / BN, (unsigned)(MB / BM)), 256, SMEM_TOTAL>>>(
        m_xh, m_wph, P_DIM / BK, nullptr, (__half*)zbuf, H_DIM);

    // 2) hps scan
    hps_scan<<<(B_DIM * H_DIM) / 256, 256>>>(b_hps);

    // 3) U = a_hps @ WhsT^T + bias_s  (K=512)
    tc_gemm<1><<<dim3(S_DIM / BN, (unsigned)(MB / BM)), 256, SMEM_TOTAL>>>(
        m_z, m_whs, H_DIM / BK, b_s, (__half*)ubuf, S_DIM);

    // 4) all 20 recurrent steps in ONE persistent launch
    rec_persist<<<R_GRID, 256, SMEM_TOTAL>>>(b_css, out);
}